// round 1
// baseline (speedup 1.0000x reference)
#include <cuda_runtime.h>

#define N_NODES 100000
#define N_EDGES 3200000
#define NFEAT   512
#define NHID    256
#define NCLASS  16
#define KITER   10

// ---------------- scratch (static device globals; no allocation) ----------------
__device__ int   g_degcnt[N_NODES];     // out-degree counts (over row)
__device__ int   g_colcnt[N_NODES];     // in-degree counts (over col)
__device__ int   g_cursor[N_NODES];     // CSR fill cursors
__device__ float g_dinv[N_NODES];       // deg^-0.5 (row-degree based)
__device__ int   g_incl[N_NODES];       // scan scratch
__device__ int   g_bsums[128];          // scan block sums
__device__ int   g_off[N_NODES + 1];    // CSR offsets (by destination col)
__device__ int   g_src[N_EDGES];        // CSR: source node per edge
__device__ float g_w[N_EDGES];          // CSR: norm weight per edge
__device__ float g_hid[(size_t)N_NODES * NHID];   // 102.4 MB MLP hidden
__device__ float g_hA[N_NODES * NCLASS];          // ping
__device__ float g_hB[N_NODES * NCLASS];          // pong

// ---------------- preprocessing ----------------
__global__ void k_zero() {
    int i = blockIdx.x * blockDim.x + threadIdx.x;
    if (i < N_NODES) { g_degcnt[i] = 0; g_colcnt[i] = 0; g_cursor[i] = 0; }
}

__global__ void k_count(const int* __restrict__ ei) {
    int e = blockIdx.x * blockDim.x + threadIdx.x;
    if (e < N_EDGES) {
        atomicAdd(&g_degcnt[ei[e]], 1);            // row (out-degree, used for norm)
        atomicAdd(&g_colcnt[ei[N_EDGES + e]], 1);  // col (in-degree, for CSR)
    }
}

__global__ void k_dinv() {
    int i = blockIdx.x * blockDim.x + threadIdx.x;
    if (i < N_NODES) {
        int d = g_degcnt[i];
        g_dinv[i] = (d > 0) ? rsqrtf((float)d) : 0.0f;
    }
}

// 3-kernel exclusive scan of g_colcnt -> g_off
__global__ void k_scan1() {
    __shared__ int s[1024];
    int t = threadIdx.x;
    int i = blockIdx.x * 1024 + t;
    int v = (i < N_NODES) ? g_colcnt[i] : 0;
    s[t] = v;
    __syncthreads();
    for (int off = 1; off < 1024; off <<= 1) {
        int a = (t >= off) ? s[t - off] : 0;
        __syncthreads();
        s[t] += a;
        __syncthreads();
    }
    if (i < N_NODES) g_incl[i] = s[t];
    if (t == 1023) g_bsums[blockIdx.x] = s[t];
}

__global__ void k_scan2(int nb) {
    if (threadIdx.x == 0 && blockIdx.x == 0) {
        int run = 0;
        for (int b = 0; b < nb; b++) { int v = g_bsums[b]; g_bsums[b] = run; run += v; }
    }
}

__global__ void k_scan3() {
    int i = blockIdx.x * blockDim.x + threadIdx.x;
    if (i < N_NODES) {
        int ex = g_incl[i] - g_colcnt[i] + g_bsums[i >> 10];
        g_off[i] = ex;
        if (i == N_NODES - 1) g_off[N_NODES] = ex + g_colcnt[i];
    }
}

__global__ void k_build(const int* __restrict__ ei) {
    int e = blockIdx.x * blockDim.x + threadIdx.x;
    if (e < N_EDGES) {
        int r = ei[e];
        int c = ei[N_EDGES + e];
        float w = g_dinv[r] * g_dinv[c];
        int pos = g_off[c] + atomicAdd(&g_cursor[c], 1);
        g_src[pos] = r;
        g_w[pos]   = w;
    }
}

// ---------------- GEMM1: hid = relu(x @ W1 + b1)  [100000x512 @ 512x256] ----------------
// 64x64 block tile, 16x16 threads, 4x4 micro-tile, K-step 16, fp32.
__global__ void k_gemm1(const float* __restrict__ x,
                        const float* __restrict__ W1,
                        const float* __restrict__ b1) {
    __shared__ float As[16][68];  // [k][m], row stride 272B (16B aligned)
    __shared__ float Bs[16][68];  // [k][n]

    int t  = threadIdx.x;
    int tx = t & 15, ty = t >> 4;
    int m0 = blockIdx.y * 64, n0 = blockIdx.x * 64;

    float acc[4][4] = {};

    int am = t >> 2, akq = t & 3;   // A: thread loads float4 of row am, k-quad akq
    int bk = t >> 4, bnq = t & 15;  // B: thread loads float4 of k-row bk, n-quad bnq

    for (int k0 = 0; k0 < NFEAT; k0 += 16) {
        int gm = m0 + am; if (gm >= N_NODES) gm = N_NODES - 1;
        float4 a4 = *(const float4*)&x[(size_t)gm * NFEAT + k0 + akq * 4];
        As[akq * 4 + 0][am] = a4.x;
        As[akq * 4 + 1][am] = a4.y;
        As[akq * 4 + 2][am] = a4.z;
        As[akq * 4 + 3][am] = a4.w;
        *(float4*)&Bs[bk][bnq * 4] =
            *(const float4*)&W1[(size_t)(k0 + bk) * NHID + n0 + bnq * 4];
        __syncthreads();

        #pragma unroll
        for (int kk = 0; kk < 16; kk++) {
            float4 av = *(float4*)&As[kk][ty * 4];
            float4 bv = *(float4*)&Bs[kk][tx * 4];
            float a[4] = {av.x, av.y, av.z, av.w};
            float b[4] = {bv.x, bv.y, bv.z, bv.w};
            #pragma unroll
            for (int i = 0; i < 4; i++)
                #pragma unroll
                for (int j = 0; j < 4; j++)
                    acc[i][j] += a[i] * b[j];
        }
        __syncthreads();
    }

    #pragma unroll
    for (int i = 0; i < 4; i++) {
        int m = m0 + ty * 4 + i;
        if (m < N_NODES) {
            #pragma unroll
            for (int j = 0; j < 4; j++) {
                int n = n0 + tx * 4 + j;
                float v = acc[i][j] + b1[n];
                g_hid[(size_t)m * NHID + n] = fmaxf(v, 0.0f);
            }
        }
    }
}

// ---------------- GEMM2: h = hid @ W2 + b2 ; out = gamma[0]*h ----------------
// 16 nodes per 256-thread block; thread = (node_local, class)
__global__ void k_gemm2(const float* __restrict__ W2,
                        const float* __restrict__ b2,
                        const float* __restrict__ gamma,
                        float* __restrict__ out) {
    __shared__ float W2s[NHID * NCLASS];     // 16 KB
    __shared__ float hs[16][NHID + 4];       // padded vs bank conflicts

    int t = threadIdx.x;
    int node0 = blockIdx.x * 16;

    for (int i = t; i < NHID * NCLASS; i += 256) W2s[i] = W2[i];
    for (int i = t; i < 16 * NHID; i += 256) {
        int nl = i >> 8, k = i & 255;
        hs[nl][k] = g_hid[(size_t)(node0 + nl) * NHID + k];
    }
    __syncthreads();

    int nl = t >> 4, c = t & 15;
    float acc = b2[c];
    #pragma unroll 8
    for (int k = 0; k < NHID; k++)
        acc += hs[nl][k] * W2s[k * NCLASS + c];

    int node = node0 + nl;
    g_hA[node * NCLASS + c] = acc;
    out[node * NCLASS + c]  = gamma[0] * acc;
}

// ---------------- propagation: h_out[n] = sum_in w*h_in[src]; out += gamma[k]*h_out ----------------
// 16 nodes per 256-thread block; 16 threads (one per class) cooperate per node.
__global__ void k_prop(int parity, const float* __restrict__ gamma, int kidx,
                       float* __restrict__ out) {
    const float* hin  = parity ? g_hB : g_hA;
    float*       hout = parity ? g_hA : g_hB;

    int t = threadIdx.x;
    int node = blockIdx.x * 16 + (t >> 4);
    int c = t & 15;

    int beg = g_off[node], end = g_off[node + 1];
    float acc = 0.0f;
    for (int j = beg; j < end; j++) {
        int   s = g_src[j];   // same addr across the 16 lanes -> broadcast
        float w = g_w[j];
        acc += w * hin[s * NCLASS + c];  // 16 lanes read one 64B row (coalesced, L2-resident)
    }
    hout[node * NCLASS + c] = acc;
    out[node * NCLASS + c] += gamma[kidx] * acc;
}

// ---------------- launch ----------------
extern "C" void kernel_launch(void* const* d_in, const int* in_sizes, int n_in,
                              void* d_out, int out_size) {
    const float* x     = (const float*)d_in[0];
    const int*   ei    = (const int*)  d_in[1];
    const float* W1    = (const float*)d_in[2];
    const float* b1    = (const float*)d_in[3];
    const float* W2    = (const float*)d_in[4];
    const float* b2    = (const float*)d_in[5];
    const float* gamma = (const float*)d_in[6];
    float* out = (float*)d_out;

    k_zero <<<(N_NODES + 255) / 256, 256>>>();
    k_count<<<(N_EDGES + 255) / 256, 256>>>(ei);
    k_dinv <<<(N_NODES + 255) / 256, 256>>>();

    int nb = (N_NODES + 1023) / 1024;
    k_scan1<<<nb, 1024>>>();
    k_scan2<<<1, 32>>>(nb);
    k_scan3<<<(N_NODES + 255) / 256, 256>>>();
    k_build<<<(N_EDGES + 255) / 256, 256>>>(ei);

    dim3 g1(NHID / 64, (N_NODES + 63) / 64);
    k_gemm1<<<g1, 256>>>(x, W1, b1);
    k_gemm2<<<N_NODES / 16, 256>>>(W2, b2, gamma, out);

    for (int k = 1; k <= KITER; k++)
        k_prop<<<N_NODES / 16, 256>>>((k - 1) & 1, gamma, k, out);
}

// round 4
// speedup vs baseline: 1.6837x; 1.6837x over previous
#include <cuda_runtime.h>
#include <cuda_bf16.h>
#include <cstdint>

#define N_NODES 100000
#define N_EDGES 3200000
#define NFEAT   512
#define NHID    256
#define NCLASS  16
#define KITER   10

// ---------------- scratch (static device globals; no allocation) ----------------
__device__ int   g_degcnt[N_NODES];
__device__ int   g_colcnt[N_NODES];
__device__ int   g_cursor[N_NODES];
__device__ float g_dinv[N_NODES];
__device__ int   g_incl[N_NODES];
__device__ int   g_bsums[128];
__device__ int   g_off[N_NODES + 1];
__device__ int   g_src[N_EDGES];
__device__ float g_hid[(size_t)N_NODES * NHID];   // COLUMN-MAJOR: g_hid[n*N_NODES + m]
__device__ float g_hA[N_NODES * NCLASS];          // ping (holds dinv-scaled y)
__device__ float g_hB[N_NODES * NCLASS];          // pong
// W1^T bf16 hi/lo planes: [NHID n][NFEAT k], k-contiguous
__device__ __align__(16) unsigned short g_bthi[NHID * NFEAT];
__device__ __align__(16) unsigned short g_btlo[NHID * NFEAT];

// ---------------- small helpers ----------------
__device__ __forceinline__ uint32_t smem_u32(const void* p) {
    uint32_t a;
    asm("{ .reg .u64 t; cvta.to.shared.u64 t, %1; cvt.u32.u64 %0, t; }" : "=r"(a) : "l"(p));
    return a;
}
__device__ __forceinline__ uint32_t prmt7632(uint32_t a, uint32_t b) {
    uint32_t r;
    asm("prmt.b32 %0, %1, %2, 0x7632;" : "=r"(r) : "r"(a), "r"(b));
    return r;
}
__device__ __forceinline__ uint32_t cvt_bf16x2(float hi, float lo) {
    uint32_t r;
    asm("cvt.rn.bf16x2.f32 %0, %1, %2;" : "=r"(r) : "f"(hi), "f"(lo));
    return r;
}
__device__ __forceinline__ void ldm_x4(uint32_t* r, uint32_t addr) {
    asm volatile("ldmatrix.sync.aligned.m8n8.x4.shared.b16 {%0,%1,%2,%3}, [%4];"
                 : "=r"(r[0]), "=r"(r[1]), "=r"(r[2]), "=r"(r[3]) : "r"(addr));
}
__device__ __forceinline__ void mma_bf16(float* d, const uint32_t* a, const uint32_t* b) {
    asm volatile("mma.sync.aligned.m16n8k16.row.col.f32.bf16.bf16.f32 "
                 "{%0,%1,%2,%3}, {%4,%5,%6,%7}, {%8,%9}, {%0,%1,%2,%3};"
                 : "+f"(d[0]), "+f"(d[1]), "+f"(d[2]), "+f"(d[3])
                 : "r"(a[0]), "r"(a[1]), "r"(a[2]), "r"(a[3]), "r"(b[0]), "r"(b[1]));
}

// ---------------- preprocessing ----------------
__global__ void k_zero() {
    int i = blockIdx.x * blockDim.x + threadIdx.x;
    if (i < N_NODES) { g_degcnt[i] = 0; g_colcnt[i] = 0; g_cursor[i] = 0; }
}
__global__ void k_count(const int* __restrict__ ei) {
    int e = blockIdx.x * blockDim.x + threadIdx.x;
    if (e < N_EDGES) {
        atomicAdd(&g_degcnt[ei[e]], 1);
        atomicAdd(&g_colcnt[ei[N_EDGES + e]], 1);
    }
}
__global__ void k_dinv() {
    int i = blockIdx.x * blockDim.x + threadIdx.x;
    if (i < N_NODES) {
        int d = g_degcnt[i];
        g_dinv[i] = (d > 0) ? rsqrtf((float)d) : 0.0f;
    }
}
__global__ void k_scan1() {
    __shared__ int s[1024];
    int t = threadIdx.x;
    int i = blockIdx.x * 1024 + t;
    int v = (i < N_NODES) ? g_colcnt[i] : 0;
    s[t] = v;
    __syncthreads();
    for (int off = 1; off < 1024; off <<= 1) {
        int a = (t >= off) ? s[t - off] : 0;
        __syncthreads();
        s[t] += a;
        __syncthreads();
    }
    if (i < N_NODES) g_incl[i] = s[t];
    if (t == 1023) g_bsums[blockIdx.x] = s[t];
}
__global__ void k_scan2(int nb) {
    if (threadIdx.x == 0 && blockIdx.x == 0) {
        int run = 0;
        for (int b = 0; b < nb; b++) { int v = g_bsums[b]; g_bsums[b] = run; run += v; }
    }
}
__global__ void k_scan3() {
    int i = blockIdx.x * blockDim.x + threadIdx.x;
    if (i < N_NODES) {
        int ex = g_incl[i] - g_colcnt[i] + g_bsums[i >> 10];
        g_off[i] = ex;
        if (i == N_NODES - 1) g_off[N_NODES] = ex + g_colcnt[i];
    }
}
__global__ void k_build(const int* __restrict__ ei) {
    int e = blockIdx.x * blockDim.x + threadIdx.x;
    if (e < N_EDGES) {
        int r = ei[e];
        int c = ei[N_EDGES + e];
        int pos = g_off[c] + atomicAdd(&g_cursor[c], 1);
        g_src[pos] = r;
    }
}

// ---------------- W1 -> W1^T bf16 hi/lo planes ----------------
__global__ void k_packW1(const float* __restrict__ W1) {
    int idx = blockIdx.x * blockDim.x + threadIdx.x;
    if (idx >= NFEAT * NHID) return;
    int k = idx >> 8, n = idx & 255;                 // W1 is [k][n]
    float v = W1[k * NHID + n];
    uint32_t b = __float_as_uint(v);
    unsigned short hi = (unsigned short)(b >> 16);   // truncate-to-bf16
    float lof = v - __uint_as_float(b & 0xFFFF0000u);
    __nv_bfloat16 lo = __float2bfloat16(lof);        // rn residual
    g_bthi[n * NFEAT + k] = hi;
    g_btlo[n * NFEAT + k] = *(unsigned short*)&lo;
}

// ---------------- GEMM1: hid_cm = relu(x @ W1 + b1), mma.sync bf16-split ----------------
// BM=128, BN=128, BK=32. 8 warps: 4(m) x 2(n); warp tile 32x64 = 2x8 m16n8 tiles.
// smem tiles padded to 80B row stride (conflict-free ldmatrix, 16B aligned).
#define TSTRIDE 80
__global__ __launch_bounds__(256) void k_gemm1(const float* __restrict__ x,
                                               const float* __restrict__ b1) {
    __shared__ __align__(16) unsigned char sAhi[128 * TSTRIDE];
    __shared__ __align__(16) unsigned char sAlo[128 * TSTRIDE];
    __shared__ __align__(16) unsigned char sBhi[128 * TSTRIDE];
    __shared__ __align__(16) unsigned char sBlo[128 * TSTRIDE];

    const int t = threadIdx.x, lane = t & 31, wid = t >> 5;
    const int wm = wid & 3, wn = wid >> 2;           // warp coords
    const int m0 = blockIdx.y * 128, n0 = blockIdx.x * 128;

    const uint32_t uAhi = smem_u32(sAhi), uAlo = smem_u32(sAlo);
    const uint32_t uBhi = smem_u32(sBhi), uBlo = smem_u32(sBlo);

    float acc[2][8][4] = {};

    // ldmatrix lane addressing (constant across chunks)
    const int aRow = (lane & 15);
    const int aKh  = (lane >> 4);
    const int bRow = (lane & 7) + ((lane >> 4) << 3);
    const int bKh  = (lane >> 3) & 1;

    const int lr = t >> 1, lh = t & 1;               // loader: row 0..127, half 0/1
    int gm = m0 + lr; if (gm >= N_NODES) gm = N_NODES - 1;
    const float* xsrc = x + (size_t)gm * NFEAT + lh * 16;
    const uint4* bHsrc = (const uint4*)(g_bthi + (size_t)(n0 + lr) * NFEAT + lh * 16);
    const uint4* bLsrc = (const uint4*)(g_btlo + (size_t)(n0 + lr) * NFEAT + lh * 16);

    for (int chunk = 0; chunk < 16; chunk++) {
        // ---- load & convert A (x fp32 -> bf16 hi/lo), copy B planes ----
        {
            const float* src = xsrc + chunk * 32;
            unsigned char* dAh = sAhi + lr * TSTRIDE + lh * 32;
            unsigned char* dAl = sAlo + lr * TSTRIDE + lh * 32;
            #pragma unroll
            for (int i = 0; i < 4; i++) {
                float4 f = *(const float4*)(src + i * 4);
                uint32_t bx = __float_as_uint(f.x), by = __float_as_uint(f.y);
                uint32_t bz = __float_as_uint(f.z), bw = __float_as_uint(f.w);
                uint32_t hi01 = prmt7632(bx, by);
                uint32_t hi23 = prmt7632(bz, bw);
                float l0 = f.x - __uint_as_float(bx & 0xFFFF0000u);
                float l1 = f.y - __uint_as_float(by & 0xFFFF0000u);
                float l2 = f.z - __uint_as_float(bz & 0xFFFF0000u);
                float l3 = f.w - __uint_as_float(bw & 0xFFFF0000u);
                uint32_t lo01 = cvt_bf16x2(l1, l0);
                uint32_t lo23 = cvt_bf16x2(l3, l2);
                *(uint2*)(dAh + i * 8) = make_uint2(hi01, hi23);
                *(uint2*)(dAl + i * 8) = make_uint2(lo01, lo23);
            }
            // FIX (R3): each chunk advances 32 halves = 4 uint4 (was 2 -> wrong K range)
            uint4 h0 = bHsrc[chunk * 4], h1 = bHsrc[chunk * 4 + 1];
            uint4 l0v = bLsrc[chunk * 4], l1v = bLsrc[chunk * 4 + 1];
            unsigned char* dBh = sBhi + lr * TSTRIDE + lh * 32;
            unsigned char* dBl = sBlo + lr * TSTRIDE + lh * 32;
            *(uint4*)(dBh) = h0; *(uint4*)(dBh + 16) = h1;
            *(uint4*)(dBl) = l0v; *(uint4*)(dBl + 16) = l1v;
        }
        __syncthreads();

        // ---- compute: 2 ksteps x (2m x 8n) x 3 combos ----
        #pragma unroll
        for (int ks = 0; ks < 2; ks++) {
            uint32_t aH[2][4], aL[2][4];
            #pragma unroll
            for (int i = 0; i < 2; i++) {
                uint32_t off = (uint32_t)(wm * 32 + i * 16 + aRow) * TSTRIDE + ks * 32 + aKh * 16;
                ldm_x4(aH[i], uAhi + off);
                ldm_x4(aL[i], uAlo + off);
            }
            uint32_t bH[8][2], bL[8][2];
            #pragma unroll
            for (int jp = 0; jp < 4; jp++) {
                uint32_t off = (uint32_t)(wn * 64 + jp * 16 + bRow) * TSTRIDE + ks * 32 + bKh * 16;
                uint32_t r[4];
                ldm_x4(r, uBhi + off);
                bH[jp * 2][0] = r[0]; bH[jp * 2][1] = r[1];
                bH[jp * 2 + 1][0] = r[2]; bH[jp * 2 + 1][1] = r[3];
                ldm_x4(r, uBlo + off);
                bL[jp * 2][0] = r[0]; bL[jp * 2][1] = r[1];
                bL[jp * 2 + 1][0] = r[2]; bL[jp * 2 + 1][1] = r[3];
            }
            #pragma unroll
            for (int i = 0; i < 2; i++)
                #pragma unroll
                for (int j = 0; j < 8; j++) {
                    mma_bf16(acc[i][j], aH[i], bH[j]);   // hi*hi
                    mma_bf16(acc[i][j], aH[i], bL[j]);   // hi*lo
                    mma_bf16(acc[i][j], aL[i], bH[j]);   // lo*hi
                }
        }
        __syncthreads();
    }

    // ---- epilogue: +bias, relu, column-major store ----
    const int mBase = m0 + wm * 32 + (lane >> 2);
    #pragma unroll
    for (int j = 0; j < 8; j++) {
        int n = n0 + wn * 64 + j * 8 + (lane & 3) * 2;
        float bv0 = __ldg(&b1[n]), bv1 = __ldg(&b1[n + 1]);
        float* c0 = g_hid + (size_t)n * N_NODES;
        float* c1 = g_hid + (size_t)(n + 1) * N_NODES;
        #pragma unroll
        for (int i = 0; i < 2; i++) {
            int m = mBase + i * 16;
            if (m < N_NODES) {
                c0[m] = fmaxf(acc[i][j][0] + bv0, 0.0f);
                c1[m] = fmaxf(acc[i][j][1] + bv1, 0.0f);
            }
            if (m + 8 < N_NODES) {
                c0[m + 8] = fmaxf(acc[i][j][2] + bv0, 0.0f);
                c1[m + 8] = fmaxf(acc[i][j][3] + bv1, 0.0f);
            }
        }
    }
}

// ---------------- GEMM2: h = hid @ W2 + b2 ; out = g0*h ; y0 = dinv*h ----------------
__global__ void k_gemm2(const float* __restrict__ W2,
                        const float* __restrict__ b2,
                        const float* __restrict__ gamma,
                        float* __restrict__ out) {
    __shared__ float W2s[NHID * NCLASS];
    __shared__ float hs[16][NHID + 4];

    int t = threadIdx.x;
    int node0 = blockIdx.x * 16;

    for (int i = t; i < NHID * NCLASS; i += 256) W2s[i] = W2[i];
    for (int i = t; i < 16 * NHID; i += 256) {
        int k = i >> 4, nl = i & 15;                     // column-major hid read
        hs[nl][k] = g_hid[(size_t)k * N_NODES + node0 + nl];
    }
    __syncthreads();

    int nl = t >> 4, c = t & 15;
    float acc = b2[c];
    #pragma unroll 8
    for (int k = 0; k < NHID; k++)
        acc += hs[nl][k] * W2s[k * NCLASS + c];

    int node = node0 + nl;
    g_hA[node * NCLASS + c] = g_dinv[node] * acc;        // y0 = dinv ⊙ h0
    out[node * NCLASS + c]  = gamma[0] * acc;
}

// ---------------- propagation (weightless gather; dinv folded at node level) ----------------
__global__ void k_prop(int parity, const float* __restrict__ gamma, int kidx,
                       float* __restrict__ out) {
    const float2* yin  = (const float2*)(parity ? g_hB : g_hA);
    float2*       ynxt = (float2*)(parity ? g_hA : g_hB);

    int t = threadIdx.x;
    int node = blockIdx.x * 32 + (t >> 3);
    int c2 = t & 7;

    int beg = g_off[node], end = g_off[node + 1];
    float ax = 0.0f, ay = 0.0f;
    for (int j = beg; j < end; j++) {
        int s = __ldg(&g_src[j]);                 // broadcast across 8 lanes
        float2 v = yin[(size_t)s * 8 + c2];       // 8 lanes read one 64B row
        ax += v.x; ay += v.y;
    }
    float di = g_dinv[node];
    float g  = gamma[kidx] * di;
    float2* o2 = (float2*)out;
    size_t oi = (size_t)node * 8 + c2;
    float2 cur = o2[oi];
    o2[oi] = make_float2(cur.x + g * ax, cur.y + g * ay);
    float d2 = di * di;
    ynxt[oi] = make_float2(d2 * ax, d2 * ay);
}

// ---------------- launch ----------------
extern "C" void kernel_launch(void* const* d_in, const int* in_sizes, int n_in,
                              void* d_out, int out_size) {
    const float* x     = (const float*)d_in[0];
    const int*   ei    = (const int*)  d_in[1];
    const float* W1    = (const float*)d_in[2];
    const float* b1    = (const float*)d_in[3];
    const float* W2    = (const float*)d_in[4];
    const float* b2    = (const float*)d_in[5];
    const float* gamma = (const float*)d_in[6];
    float* out = (float*)d_out;

    k_packW1<<<(NFEAT * NHID + 255) / 256, 256>>>(W1);

    k_zero <<<(N_NODES + 255) / 256, 256>>>();
    k_count<<<(N_EDGES + 255) / 256, 256>>>(ei);
    k_dinv <<<(N_NODES + 255) / 256, 256>>>();

    int nb = (N_NODES + 1023) / 1024;
    k_scan1<<<nb, 1024>>>();
    k_scan2<<<1, 32>>>(nb);
    k_scan3<<<(N_NODES + 255) / 256, 256>>>();
    k_build<<<(N_EDGES + 255) / 256, 256>>>(ei);

    dim3 g1(1, (N_NODES + 127) / 128);
    g1.x = NHID / 128;                                   // n-fast for L2 reuse of x
    k_gemm1<<<g1, 256>>>(x, b1);
    k_gemm2<<<N_NODES / 16, 256>>>(W2, b2, gamma, out);

    for (int k = 1; k <= KITER; k++)
        k_prop<<<(N_NODES + 31) / 32, 256>>>((k - 1) & 1, gamma, k, out);
}

// round 5
// speedup vs baseline: 1.6889x; 1.0031x over previous
#include <cuda_runtime.h>
#include <cuda_bf16.h>
#include <cstdint>

#define N_NODES 100000
#define N_EDGES 3200000
#define NFEAT   512
#define NHID    256
#define NCLASS  16
#define KITER   10

// ---------------- scratch (static device globals; no allocation) ----------------
__device__ int   g_degcnt[N_NODES];
__device__ int   g_colcnt[N_NODES];
__device__ int   g_cursor[N_NODES];
__device__ float g_dinv[N_NODES];
__device__ int   g_incl[N_NODES];
__device__ int   g_bsums[128];
__device__ int   g_off[N_NODES + 1];
__device__ int   g_src[N_EDGES];
__device__ float g_hid[(size_t)N_NODES * NHID];   // COLUMN-MAJOR: g_hid[n*N_NODES + m]
__device__ float g_hA[N_NODES * NCLASS];          // ping (holds dinv-scaled y)
__device__ float g_hB[N_NODES * NCLASS];          // pong
// W1^T bf16 hi/lo planes: [NHID n][NFEAT k], k-contiguous
__device__ __align__(16) unsigned short g_bthi[NHID * NFEAT];
__device__ __align__(16) unsigned short g_btlo[NHID * NFEAT];

// ---------------- small helpers ----------------
__device__ __forceinline__ uint32_t smem_u32(const void* p) {
    uint32_t a;
    asm("{ .reg .u64 t; cvta.to.shared.u64 t, %1; cvt.u32.u64 %0, t; }" : "=r"(a) : "l"(p));
    return a;
}
__device__ __forceinline__ uint32_t prmt7632(uint32_t a, uint32_t b) {
    uint32_t r;
    asm("prmt.b32 %0, %1, %2, 0x7632;" : "=r"(r) : "r"(a), "r"(b));
    return r;
}
__device__ __forceinline__ uint32_t cvt_bf16x2(float hi, float lo) {
    uint32_t r;
    asm("cvt.rn.bf16x2.f32 %0, %1, %2;" : "=r"(r) : "f"(hi), "f"(lo));
    return r;
}
__device__ __forceinline__ void ldm_x4(uint32_t* r, uint32_t addr) {
    asm volatile("ldmatrix.sync.aligned.m8n8.x4.shared.b16 {%0,%1,%2,%3}, [%4];"
                 : "=r"(r[0]), "=r"(r[1]), "=r"(r[2]), "=r"(r[3]) : "r"(addr));
}
__device__ __forceinline__ void mma_bf16(float* d, const uint32_t* a, const uint32_t* b) {
    asm volatile("mma.sync.aligned.m16n8k16.row.col.f32.bf16.bf16.f32 "
                 "{%0,%1,%2,%3}, {%4,%5,%6,%7}, {%8,%9}, {%0,%1,%2,%3};"
                 : "+f"(d[0]), "+f"(d[1]), "+f"(d[2]), "+f"(d[3])
                 : "r"(a[0]), "r"(a[1]), "r"(a[2]), "r"(a[3]), "r"(b[0]), "r"(b[1]));
}
__device__ __forceinline__ void cp16(uint32_t dst, const void* src) {
    asm volatile("cp.async.cg.shared.global [%0], [%1], 16;" :: "r"(dst), "l"(src) : "memory");
}
#define CP_COMMIT() asm volatile("cp.async.commit_group;" ::: "memory")
#define CP_WAIT0()  asm volatile("cp.async.wait_group 0;" ::: "memory")

// ---------------- preprocessing ----------------
__global__ void k_zero() {
    int i = blockIdx.x * blockDim.x + threadIdx.x;
    if (i < N_NODES) { g_degcnt[i] = 0; g_colcnt[i] = 0; g_cursor[i] = 0; }
}
__global__ void k_count(const int* __restrict__ ei) {
    int e = blockIdx.x * blockDim.x + threadIdx.x;
    if (e < N_EDGES) {
        atomicAdd(&g_degcnt[ei[e]], 1);
        atomicAdd(&g_colcnt[ei[N_EDGES + e]], 1);
    }
}
__global__ void k_dinv() {
    int i = blockIdx.x * blockDim.x + threadIdx.x;
    if (i < N_NODES) {
        int d = g_degcnt[i];
        g_dinv[i] = (d > 0) ? rsqrtf((float)d) : 0.0f;
    }
}
__global__ void k_scan1() {
    __shared__ int s[1024];
    int t = threadIdx.x;
    int i = blockIdx.x * 1024 + t;
    int v = (i < N_NODES) ? g_colcnt[i] : 0;
    s[t] = v;
    __syncthreads();
    for (int off = 1; off < 1024; off <<= 1) {
        int a = (t >= off) ? s[t - off] : 0;
        __syncthreads();
        s[t] += a;
        __syncthreads();
    }
    if (i < N_NODES) g_incl[i] = s[t];
    if (t == 1023) g_bsums[blockIdx.x] = s[t];
}
__global__ void k_scan2(int nb) {
    if (threadIdx.x == 0 && blockIdx.x == 0) {
        int run = 0;
        for (int b = 0; b < nb; b++) { int v = g_bsums[b]; g_bsums[b] = run; run += v; }
    }
}
__global__ void k_scan3() {
    int i = blockIdx.x * blockDim.x + threadIdx.x;
    if (i < N_NODES) {
        int ex = g_incl[i] - g_colcnt[i] + g_bsums[i >> 10];
        g_off[i] = ex;
        if (i == N_NODES - 1) g_off[N_NODES] = ex + g_colcnt[i];
    }
}
__global__ void k_build(const int* __restrict__ ei) {
    int e = blockIdx.x * blockDim.x + threadIdx.x;
    if (e < N_EDGES) {
        int r = ei[e];
        int c = ei[N_EDGES + e];
        int pos = g_off[c] + atomicAdd(&g_cursor[c], 1);
        g_src[pos] = r;
    }
}

// ---------------- W1 -> W1^T bf16 hi/lo planes ----------------
__global__ void k_packW1(const float* __restrict__ W1) {
    int idx = blockIdx.x * blockDim.x + threadIdx.x;
    if (idx >= NFEAT * NHID) return;
    int k = idx >> 8, n = idx & 255;                 // W1 is [k][n]
    float v = W1[k * NHID + n];
    uint32_t b = __float_as_uint(v);
    unsigned short hi = (unsigned short)(b >> 16);   // truncate-to-bf16
    float lof = v - __uint_as_float(b & 0xFFFF0000u);
    __nv_bfloat16 lo = __float2bfloat16(lof);        // rn residual
    g_bthi[n * NFEAT + k] = hi;
    g_btlo[n * NFEAT + k] = *(unsigned short*)&lo;
}

// ---------------- GEMM1: hid_cm = relu(x @ W1 + b1), mma.sync bf16-split, pipelined ----------------
// BM=128, BN=128, BK=32. 8 warps: 4(m) x 2(n); warp tile 32x64 = 2x8 m16n8 tiles.
// Double-buffered smem (2 stages x 4 planes x 128 x 80B = 80KB dynamic).
// A: register-prefetch + in-reg bf16 split. B: cp.async 16B copies.
#define TSTRIDE 80
#define PLANE   (128 * TSTRIDE)          // 10240
#define STAGE   (4 * PLANE)              // 40960
#define SMEM_G1 (2 * STAGE)              // 81920
__global__ __launch_bounds__(256, 1) void k_gemm1(const float* __restrict__ x,
                                                  const float* __restrict__ b1) {
    extern __shared__ __align__(16) unsigned char smem[];
    // plane order within stage: Ahi, Alo, Bhi, Blo
    const uint32_t sb = smem_u32(smem);

    const int t = threadIdx.x, lane = t & 31, wid = t >> 5;
    const int wm = wid & 3, wn = wid >> 2;
    const int m0 = blockIdx.y * 128, n0 = blockIdx.x * 128;

    float acc[2][8][4] = {};

    const int aRow = (lane & 15);
    const int aKh  = (lane >> 4);
    const int bRow = (lane & 7) + ((lane >> 4) << 3);
    const int bKh  = (lane >> 3) & 1;

    const int lr = t >> 1, lh = t & 1;               // loader: row 0..127, half 0/1
    int gm = m0 + lr; if (gm >= N_NODES) gm = N_NODES - 1;
    const float* xsrc = x + (size_t)gm * NFEAT + lh * 16;
    const uint4* bHsrc = (const uint4*)(g_bthi + (size_t)(n0 + lr) * NFEAT + lh * 16);
    const uint4* bLsrc = (const uint4*)(g_btlo + (size_t)(n0 + lr) * NFEAT + lh * 16);
    const uint32_t ldOff = (uint32_t)(lr * TSTRIDE + lh * 32);

    float4 fA[4];

    // ---- prologue: stage 0 ----
    #pragma unroll
    for (int i = 0; i < 4; i++) fA[i] = *(const float4*)(xsrc + i * 4);
    cp16(sb + 2 * PLANE + ldOff,      &bHsrc[0]);
    cp16(sb + 2 * PLANE + ldOff + 16, &bHsrc[1]);
    cp16(sb + 3 * PLANE + ldOff,      &bLsrc[0]);
    cp16(sb + 3 * PLANE + ldOff + 16, &bLsrc[1]);
    CP_COMMIT();
    {
        unsigned char* dAh = smem + ldOff;
        unsigned char* dAl = smem + PLANE + ldOff;
        #pragma unroll
        for (int i = 0; i < 4; i++) {
            float4 f = fA[i];
            uint32_t bx = __float_as_uint(f.x), by = __float_as_uint(f.y);
            uint32_t bz = __float_as_uint(f.z), bw = __float_as_uint(f.w);
            *(uint2*)(dAh + i * 8) = make_uint2(prmt7632(bx, by), prmt7632(bz, bw));
            float l0 = f.x - __uint_as_float(bx & 0xFFFF0000u);
            float l1 = f.y - __uint_as_float(by & 0xFFFF0000u);
            float l2 = f.z - __uint_as_float(bz & 0xFFFF0000u);
            float l3 = f.w - __uint_as_float(bw & 0xFFFF0000u);
            *(uint2*)(dAl + i * 8) = make_uint2(cvt_bf16x2(l1, l0), cvt_bf16x2(l3, l2));
        }
    }
    CP_WAIT0();
    __syncthreads();

    for (int chunk = 0; chunk < 16; chunk++) {
        const uint32_t cur = (chunk & 1) * STAGE;
        const uint32_t nxt = STAGE - cur;
        const bool more = (chunk < 15);

        // ---- issue next-chunk loads (hidden under the MMA phase) ----
        if (more) {
            cp16(sb + nxt + 2 * PLANE + ldOff,      &bHsrc[(chunk + 1) * 4]);
            cp16(sb + nxt + 2 * PLANE + ldOff + 16, &bHsrc[(chunk + 1) * 4 + 1]);
            cp16(sb + nxt + 3 * PLANE + ldOff,      &bLsrc[(chunk + 1) * 4]);
            cp16(sb + nxt + 3 * PLANE + ldOff + 16, &bLsrc[(chunk + 1) * 4 + 1]);
            CP_COMMIT();
            const float* src = xsrc + (chunk + 1) * 32;
            #pragma unroll
            for (int i = 0; i < 4; i++) fA[i] = *(const float4*)(src + i * 4);
        }

        // ---- compute current stage ----
        const uint32_t uAhi = sb + cur, uAlo = sb + cur + PLANE;
        const uint32_t uBhi = sb + cur + 2 * PLANE, uBlo = sb + cur + 3 * PLANE;
        #pragma unroll
        for (int ks = 0; ks < 2; ks++) {
            uint32_t aH[2][4], aL[2][4];
            #pragma unroll
            for (int i = 0; i < 2; i++) {
                uint32_t off = (uint32_t)(wm * 32 + i * 16 + aRow) * TSTRIDE + ks * 32 + aKh * 16;
                ldm_x4(aH[i], uAhi + off);
                ldm_x4(aL[i], uAlo + off);
            }
            uint32_t bH[8][2], bL[8][2];
            #pragma unroll
            for (int jp = 0; jp < 4; jp++) {
                uint32_t off = (uint32_t)(wn * 64 + jp * 16 + bRow) * TSTRIDE + ks * 32 + bKh * 16;
                uint32_t r[4];
                ldm_x4(r, uBhi + off);
                bH[jp * 2][0] = r[0]; bH[jp * 2][1] = r[1];
                bH[jp * 2 + 1][0] = r[2]; bH[jp * 2 + 1][1] = r[3];
                ldm_x4(r, uBlo + off);
                bL[jp * 2][0] = r[0]; bL[jp * 2][1] = r[1];
                bL[jp * 2 + 1][0] = r[2]; bL[jp * 2 + 1][1] = r[3];
            }
            #pragma unroll
            for (int i = 0; i < 2; i++)
                #pragma unroll
                for (int j = 0; j < 8; j++) {
                    mma_bf16(acc[i][j], aH[i], bH[j]);   // hi*hi
                    mma_bf16(acc[i][j], aH[i], bL[j]);   // hi*lo
                    mma_bf16(acc[i][j], aL[i], bH[j]);   // lo*hi
                }
        }

        // ---- convert prefetched A into next stage ----
        if (more) {
            unsigned char* dAh = smem + nxt + ldOff;
            unsigned char* dAl = smem + nxt + PLANE + ldOff;
            #pragma unroll
            for (int i = 0; i < 4; i++) {
                float4 f = fA[i];
                uint32_t bx = __float_as_uint(f.x), by = __float_as_uint(f.y);
                uint32_t bz = __float_as_uint(f.z), bw = __float_as_uint(f.w);
                *(uint2*)(dAh + i * 8) = make_uint2(prmt7632(bx, by), prmt7632(bz, bw));
                float l0 = f.x - __uint_as_float(bx & 0xFFFF0000u);
                float l1 = f.y - __uint_as_float(by & 0xFFFF0000u);
                float l2 = f.z - __uint_as_float(bz & 0xFFFF0000u);
                float l3 = f.w - __uint_as_float(bw & 0xFFFF0000u);
                *(uint2*)(dAl + i * 8) = make_uint2(cvt_bf16x2(l1, l0), cvt_bf16x2(l3, l2));
            }
            CP_WAIT0();
        }
        __syncthreads();
    }

    // ---- epilogue: +bias, relu, column-major store ----
    const int mBase = m0 + wm * 32 + (lane >> 2);
    #pragma unroll
    for (int j = 0; j < 8; j++) {
        int n = n0 + wn * 64 + j * 8 + (lane & 3) * 2;
        float bv0 = __ldg(&b1[n]), bv1 = __ldg(&b1[n + 1]);
        float* c0 = g_hid + (size_t)n * N_NODES;
        float* c1 = g_hid + (size_t)(n + 1) * N_NODES;
        #pragma unroll
        for (int i = 0; i < 2; i++) {
            int m = mBase + i * 16;
            if (m < N_NODES) {
                c0[m] = fmaxf(acc[i][j][0] + bv0, 0.0f);
                c1[m] = fmaxf(acc[i][j][1] + bv1, 0.0f);
            }
            if (m + 8 < N_NODES) {
                c0[m + 8] = fmaxf(acc[i][j][2] + bv0, 0.0f);
                c1[m + 8] = fmaxf(acc[i][j][3] + bv1, 0.0f);
            }
        }
    }
}

// ---------------- GEMM2: h = hid @ W2 + b2 ; out = g0*h ; y0 = dinv*h ----------------
__global__ void k_gemm2(const float* __restrict__ W2,
                        const float* __restrict__ b2,
                        const float* __restrict__ gamma,
                        float* __restrict__ out) {
    __shared__ float W2s[NHID * NCLASS];
    __shared__ float hs[16][NHID + 4];

    int t = threadIdx.x;
    int node0 = blockIdx.x * 16;

    for (int i = t; i < NHID * NCLASS; i += 256) W2s[i] = W2[i];
    for (int i = t; i < 16 * NHID; i += 256) {
        int k = i >> 4, nl = i & 15;                     // column-major hid read
        hs[nl][k] = g_hid[(size_t)k * N_NODES + node0 + nl];
    }
    __syncthreads();

    int nl = t >> 4, c = t & 15;
    float acc = b2[c];
    #pragma unroll 8
    for (int k = 0; k < NHID; k++)
        acc += hs[nl][k] * W2s[k * NCLASS + c];

    int node = node0 + nl;
    g_hA[node * NCLASS + c] = g_dinv[node] * acc;        // y0 = dinv ⊙ h0
    out[node * NCLASS + c]  = gamma[0] * acc;
}

// ---------------- propagation (weightless gather; dinv folded at node level) ----------------
__global__ void k_prop(int parity, const float* __restrict__ gamma, int kidx,
                       float* __restrict__ out) {
    const float2* yin  = (const float2*)(parity ? g_hB : g_hA);
    float2*       ynxt = (float2*)(parity ? g_hA : g_hB);

    int t = threadIdx.x;
    int node = blockIdx.x * 32 + (t >> 3);
    int c2 = t & 7;

    int beg = g_off[node], end = g_off[node + 1];
    float ax = 0.0f, ay = 0.0f;
    for (int j = beg; j < end; j++) {
        int s = __ldg(&g_src[j]);                 // broadcast across 8 lanes
        float2 v = yin[(size_t)s * 8 + c2];       // 8 lanes read one 64B row
        ax += v.x; ay += v.y;
    }
    float di = g_dinv[node];
    float g  = gamma[kidx] * di;
    float2* o2 = (float2*)out;
    size_t oi = (size_t)node * 8 + c2;
    float2 cur = o2[oi];
    o2[oi] = make_float2(cur.x + g * ax, cur.y + g * ay);
    float d2 = di * di;
    ynxt[oi] = make_float2(d2 * ax, d2 * ay);
}

// ---------------- launch ----------------
extern "C" void kernel_launch(void* const* d_in, const int* in_sizes, int n_in,
                              void* d_out, int out_size) {
    const float* x     = (const float*)d_in[0];
    const int*   ei    = (const int*)  d_in[1];
    const float* W1    = (const float*)d_in[2];
    const float* b1    = (const float*)d_in[3];
    const float* W2    = (const float*)d_in[4];
    const float* b2    = (const float*)d_in[5];
    const float* gamma = (const float*)d_in[6];
    float* out = (float*)d_out;

    // gemm1 placed as 4th launch so ncu's skip-N sampling lands on it.
    k_packW1<<<(NFEAT * NHID + 255) / 256, 256>>>(W1);
    k_zero <<<(N_NODES + 255) / 256, 256>>>();
    k_count<<<(N_EDGES + 255) / 256, 256>>>(ei);

    cudaFuncSetAttribute(k_gemm1, cudaFuncAttributeMaxDynamicSharedMemorySize, SMEM_G1);
    dim3 g1(NHID / 128, (N_NODES + 127) / 128);
    k_gemm1<<<g1, 256, SMEM_G1>>>(x, b1);

    k_dinv <<<(N_NODES + 255) / 256, 256>>>();
    int nb = (N_NODES + 1023) / 1024;
    k_scan1<<<nb, 1024>>>();
    k_scan2<<<1, 32>>>(nb);
    k_scan3<<<(N_NODES + 255) / 256, 256>>>();
    k_build<<<(N_EDGES + 255) / 256, 256>>>(ei);

    k_gemm2<<<N_NODES / 16, 256>>>(W2, b2, gamma, out);

    for (int k = 1; k <= KITER; k++)
        k_prop<<<(N_NODES + 31) / 32, 256>>>((k - 1) & 1, gamma, k, out);
}